// round 1
// baseline (speedup 1.0000x reference)
#include <cuda_runtime.h>

#define NNODES 50000
#define NEDGES 800000
#define DIM 64
#define LAYERS 5
#define BN_EPS 1e-5f

// Scratch (allocation-free rule: __device__ globals)
__device__ float g_H[NNODES * DIM];        // node features (layer input)
__device__ float g_Z[NNODES * DIM];        // GIN combine accumulator, then reused as P2
__device__ float g_P1[NNODES * 2 * DIM];   // hidden activations [N,128]
__device__ float g_stats[512];             // [0:128) sum1, [128:256) sq1, [256:320) sum2, [320:384) sq2

// ---------------------------------------------------------------- init: h = node_emb[x]
__global__ void k_init(const int* __restrict__ x, const float* __restrict__ emb) {
    int i = blockIdx.x * blockDim.x + threadIdx.x;
    if (i < NNODES * DIM) {
        int n = i >> 6, d = i & 63;
        g_H[i] = emb[x[n] * DIM + d];
    }
}

// ------------------------------------------------- z = (1+eps)*h ; zero stats buffers
__global__ void k_zinit(const float* __restrict__ epsp) {
    int i = blockIdx.x * blockDim.x + threadIdx.x;
    float ev = 1.0f + *epsp;
    if (i < 512) g_stats[i] = 0.0f;
    if (i < NNODES * DIM) g_Z[i] = ev * g_H[i];
}

// ------------------------- edge stage: msg = relu(h[src] + ea@We + be); Z[dst] += msg
// One warp per edge; lane owns features {2l, 2l+1}; We kept in registers.
__global__ void k_edge(const int* __restrict__ ei, const float* __restrict__ ea,
                       const float* __restrict__ We, const float* __restrict__ be) {
    int lane = threadIdx.x & 31;
    int warp = (blockIdx.x * blockDim.x + threadIdx.x) >> 5;
    int nw   = (gridDim.x * blockDim.x) >> 5;

    float2 w[7];
#pragma unroll
    for (int k = 0; k < 7; k++) w[k] = *(const float2*)(We + k * DIM + 2 * lane);
    float2 bv = *(const float2*)(be + 2 * lane);

    for (int e = warp; e < NEDGES; e += nw) {
        int s = __ldg(ei + e);
        int t = __ldg(ei + NEDGES + e);
        const float* ep = ea + e * 7;
        float m0 = bv.x, m1 = bv.y;
#pragma unroll
        for (int k = 0; k < 7; k++) {
            float a = __ldg(ep + k);
            m0 = fmaf(a, w[k].x, m0);
            m1 = fmaf(a, w[k].y, m1);
        }
        float2 hv = *(const float2*)(g_H + s * DIM + 2 * lane);
        m0 = fmaxf(m0 + hv.x, 0.0f);
        m1 = fmaxf(m1 + hv.y, 0.0f);
        float* zp = g_Z + t * DIM + 2 * lane;
        atomicAdd(zp, m0);
        atomicAdd(zp + 1, m1);
    }
}

// ----------------------------------------- GEMM1: P1 = Z @ W1 + b1   ([N,64]x[64,128])
// Block: 32 rows x 128 cols, 256 threads, 4x4 register tile per thread.
__global__ void k_gemm1(const float* __restrict__ W1, const float* __restrict__ b1) {
    __shared__ float zs[32 * 64];
    __shared__ float ws[64 * 128];
    int t = threadIdx.x;
    int row0 = blockIdx.x * 32;

    for (int idx = t; idx < 64 * 128; idx += 256) ws[idx] = W1[idx];
    for (int idx = t; idx < 32 * 64; idx += 256) {
        int r = idx >> 6;
        int gr = row0 + r;
        zs[idx] = (gr < NNODES) ? g_Z[gr * 64 + (idx & 63)] : 0.0f;
    }
    __syncthreads();

    int jg = t & 31, rg = t >> 5;       // warp = one row-group -> broadcast LDS, conflict-free
    int j4 = jg * 4, r4 = rg * 4;
    float acc[4][4];
#pragma unroll
    for (int i = 0; i < 4; i++)
#pragma unroll
        for (int j = 0; j < 4; j++) acc[i][j] = 0.0f;

#pragma unroll 4
    for (int k = 0; k < 64; k++) {
        float4 wv = *(const float4*)(ws + k * 128 + j4);
#pragma unroll
        for (int i = 0; i < 4; i++) {
            float z = zs[(r4 + i) * 64 + k];
            acc[i][0] = fmaf(z, wv.x, acc[i][0]);
            acc[i][1] = fmaf(z, wv.y, acc[i][1]);
            acc[i][2] = fmaf(z, wv.z, acc[i][2]);
            acc[i][3] = fmaf(z, wv.w, acc[i][3]);
        }
    }

    float4 bvv = *(const float4*)(b1 + j4);
#pragma unroll
    for (int i = 0; i < 4; i++) {
        int gr = row0 + r4 + i;
        if (gr < NNODES) {
            float4 o;
            o.x = acc[i][0] + bvv.x;
            o.y = acc[i][1] + bvv.y;
            o.z = acc[i][2] + bvv.z;
            o.w = acc[i][3] + bvv.w;
            *(float4*)(g_P1 + gr * 128 + j4) = o;
        }
    }
}

// ----------------------------- column stats (sum, sumsq) over rows, for training BN
__global__ void k_stats1() {  // over g_P1 [N,128] -> g_stats[0..256)
    int j = threadIdx.x;  // blockDim = 128
    int rows_per = (NNODES + gridDim.x - 1) / gridDim.x;
    int r0 = blockIdx.x * rows_per;
    int r1 = min(r0 + rows_per, NNODES);
    float s = 0.0f, q = 0.0f;
    for (int r = r0; r < r1; r++) {
        float v = g_P1[r * 128 + j];
        s += v; q += v * v;
    }
    atomicAdd(g_stats + j, s);
    atomicAdd(g_stats + 128 + j, q);
}

__global__ void k_stats2() {  // over g_Z (=P2) [N,64] -> g_stats[256..384)
    int j = threadIdx.x;  // blockDim = 64
    int rows_per = (NNODES + gridDim.x - 1) / gridDim.x;
    int r0 = blockIdx.x * rows_per;
    int r1 = min(r0 + rows_per, NNODES);
    float s = 0.0f, q = 0.0f;
    for (int r = r0; r < r1; r++) {
        float v = g_Z[r * 64 + j];
        s += v; q += v * v;
    }
    atomicAdd(g_stats + 256 + j, s);
    atomicAdd(g_stats + 256 + 64 + j, q);
}

// ----------------------------------------- BN1 + ReLU, in-place on g_P1
__global__ void k_bn1(const float* __restrict__ g, const float* __restrict__ bb) {
    int i = blockIdx.x * blockDim.x + threadIdx.x;
    if (i >= NNODES * 128) return;
    int j = i & 127;
    const float inv = 1.0f / (float)NNODES;
    float m  = g_stats[j] * inv;
    float v  = g_stats[128 + j] * inv - m * m;
    float rs = rsqrtf(v + BN_EPS);
    float val = (g_P1[i] - m) * rs * g[j] + bb[j];
    g_P1[i] = fmaxf(val, 0.0f);
}

// ----------------------------------------- GEMM2: P2 = A @ W2 + b2   ([N,128]x[128,64])
// Block: 32 rows x 64 cols, 256 threads, 4x2 register tile per thread. (48KB smem)
__global__ void k_gemm2(const float* __restrict__ W2, const float* __restrict__ b2) {
    __shared__ float as[32 * 128];
    __shared__ float ws[128 * 64];
    int t = threadIdx.x;
    int row0 = blockIdx.x * 32;

    for (int idx = t; idx < 128 * 64; idx += 256) ws[idx] = W2[idx];
    for (int idx = t; idx < 32 * 128; idx += 256) {
        int r = idx >> 7;
        int gr = row0 + r;
        as[idx] = (gr < NNODES) ? g_P1[gr * 128 + (idx & 127)] : 0.0f;
    }
    __syncthreads();

    int jg = t & 31, rg = t >> 5;
    int j2 = jg * 2, r4 = rg * 4;
    float acc[4][2];
#pragma unroll
    for (int i = 0; i < 4; i++) { acc[i][0] = 0.0f; acc[i][1] = 0.0f; }

#pragma unroll 4
    for (int k = 0; k < 128; k++) {
        float2 wv = *(const float2*)(ws + k * 64 + j2);
#pragma unroll
        for (int i = 0; i < 4; i++) {
            float a = as[(r4 + i) * 128 + k];
            acc[i][0] = fmaf(a, wv.x, acc[i][0]);
            acc[i][1] = fmaf(a, wv.y, acc[i][1]);
        }
    }

    float2 bvv = *(const float2*)(b2 + j2);
#pragma unroll
    for (int i = 0; i < 4; i++) {
        int gr = row0 + r4 + i;
        if (gr < NNODES) {
            float2 o;
            o.x = acc[i][0] + bvv.x;
            o.y = acc[i][1] + bvv.y;
            *(float2*)(g_Z + gr * 64 + j2) = o;
        }
    }
}

// ----------------------------------------- BN2 (+optional ReLU): g_Z -> out (or g_H)
__global__ void k_bn2(const float* __restrict__ g, const float* __restrict__ bb,
                      float* __restrict__ out, int relu) {
    int i = blockIdx.x * blockDim.x + threadIdx.x;
    if (i >= NNODES * 64) return;
    int j = i & 63;
    const float inv = 1.0f / (float)NNODES;
    float m  = g_stats[256 + j] * inv;
    float v  = g_stats[256 + 64 + j] * inv - m * m;
    float rs = rsqrtf(v + BN_EPS);
    float val = (g_Z[i] - m) * rs * g[j] + bb[j];
    if (relu) val = fmaxf(val, 0.0f);
    float* dst = out ? out : g_H;     // nullptr -> write device-global H
    dst[i] = val;
}

extern "C" void kernel_launch(void* const* d_in, const int* in_sizes, int n_in,
                              void* d_out, int out_size) {
    const int*   x    = (const int*)d_in[0];
    const int*   ei   = (const int*)d_in[1];     // [2,E]
    const float* ea   = (const float*)d_in[2];   // [E,7]
    const float* emb  = (const float*)d_in[3];   // [1,64]
    const float* We   = (const float*)d_in[4];   // [L,7,64]
    const float* be   = (const float*)d_in[5];   // [L,64]
    const float* eps  = (const float*)d_in[6];   // [L]
    const float* W1   = (const float*)d_in[7];   // [L,64,128]
    const float* b1   = (const float*)d_in[8];   // [L,128]
    const float* g1   = (const float*)d_in[9];   // [L,128]
    const float* bb1  = (const float*)d_in[10];  // [L,128]
    const float* W2   = (const float*)d_in[11];  // [L,128,64]
    const float* b2   = (const float*)d_in[12];  // [L,64]
    const float* g2   = (const float*)d_in[13];  // [L,64]
    const float* bb2  = (const float*)d_in[14];  // [L,64]
    float* out = (float*)d_out;

    const int elemBlocks64  = (NNODES * 64 + 255) / 256;    // 12500
    const int elemBlocks128 = (NNODES * 128 + 255) / 256;   // 25000
    const int gemmBlocks    = (NNODES + 31) / 32;           // 1563

    k_init<<<elemBlocks64, 256>>>(x, emb);

    for (int l = 0; l < LAYERS; l++) {
        k_zinit<<<elemBlocks64, 256>>>(eps + l);
        k_edge<<<2048, 256>>>(ei, ea, We + l * 7 * 64, be + l * 64);
        k_gemm1<<<gemmBlocks, 256>>>(W1 + l * 64 * 128, b1 + l * 128);
        k_stats1<<<400, 128>>>();
        k_bn1<<<elemBlocks128, 256>>>(g1 + l * 128, bb1 + l * 128);
        k_gemm2<<<gemmBlocks, 256>>>(W2 + l * 128 * 64, b2 + l * 64);
        k_stats2<<<400, 64>>>();
        if (l == LAYERS - 1) {
            k_bn2<<<elemBlocks64, 256>>>(g2 + l * 64, bb2 + l * 64, out, 0);
        } else {
            k_bn2<<<elemBlocks64, 256>>>(g2 + l * 64, bb2 + l * 64, nullptr, 1);
        }
    }
}

// round 4
// speedup vs baseline: 1.3960x; 1.3960x over previous
#include <cuda_runtime.h>

#define NNODES 50000
#define NEDGES 800000
#define DIM 64
#define LAYERS 5
#define BN_EPS 1e-5f

// Scratch (__device__ globals; allocation-free rule)
__device__ float g_H[NNODES * DIM];        // node features (layer input)
__device__ float g_AGG[NNODES * DIM];      // edge-aggregation accumulator
__device__ float g_P1[NNODES * 2 * DIM];   // hidden activations [N,128]
__device__ float g_P2[NNODES * DIM];       // mlp output pre-BN2 [N,64]
__device__ float g_stats[512];             // [0:128) sum1 [128:256) sq1 [256:320) sum2 [320:384) sq2

// ---- packed f32x2 helpers ----
__device__ __forceinline__ unsigned long long pk2(float lo, float hi) {
    unsigned long long r;
    asm("mov.b64 %0, {%1, %2};" : "=l"(r) : "f"(lo), "f"(hi));
    return r;
}
__device__ __forceinline__ void upk2(unsigned long long v, float& lo, float& hi) {
    asm("mov.b64 {%0, %1}, %2;" : "=f"(lo), "=f"(hi) : "l"(v));
}
__device__ __forceinline__ void fma2(unsigned long long& d, unsigned long long a,
                                     unsigned long long b) {
    asm("fma.rn.f32x2 %0, %1, %2, %3;" : "=l"(d) : "l"(a), "l"(b), "l"(d));
}

// ---------------------------------------------------------------- init
__global__ void k_init(const int* __restrict__ x, const float* __restrict__ emb) {
    int i = blockIdx.x * blockDim.x + threadIdx.x;
    if (i < 512) g_stats[i] = 0.0f;
    if (i < NNODES * DIM) {
        int n = i >> 6, d = i & 63;
        g_H[i] = emb[x[n] * DIM + d];
        g_AGG[i] = 0.0f;
    }
}

// -------- edge stage: AGG[dst] += relu(h[src] + ea@We + be). Half-warp per edge,
// lane owns 4 features, one red.global.add.v4.f32 per lane (16 REDs/edge).
// Block 0 also zeroes ALL 512 stats entries for this layer (2 per thread).
__global__ void k_edge(const int* __restrict__ ei, const float* __restrict__ ea,
                       const float* __restrict__ We, const float* __restrict__ be) {
    if (blockIdx.x == 0) {
        g_stats[threadIdx.x] = 0.0f;          // [0:256)
        g_stats[256 + threadIdx.x] = 0.0f;    // [256:512)
    }

    int t = blockIdx.x * blockDim.x + threadIdx.x;
    int lane = t & 31;
    int sub = lane >> 4;          // 0/1: which edge of this warp's pair
    int sl = lane & 15;           // feature group: 4 floats
    int warp = t >> 5;
    int nslots = (gridDim.x * blockDim.x) >> 4;   // 2 edges per warp

    float4 w[7];
#pragma unroll
    for (int k = 0; k < 7; k++) w[k] = *(const float4*)(We + k * DIM + 4 * sl);
    float4 b4 = *(const float4*)(be + 4 * sl);

    for (int e = warp * 2 + sub; e < NEDGES; e += nslots) {
        int s = __ldg(ei + e);
        int d = __ldg(ei + NEDGES + e);
        const float* ep = ea + e * 7;
        float4 m = b4;
#pragma unroll
        for (int k = 0; k < 7; k++) {
            float a = __ldg(ep + k);
            m.x = fmaf(a, w[k].x, m.x);
            m.y = fmaf(a, w[k].y, m.y);
            m.z = fmaf(a, w[k].z, m.z);
            m.w = fmaf(a, w[k].w, m.w);
        }
        float4 h4 = *(const float4*)(g_H + s * DIM + 4 * sl);
        m.x = fmaxf(m.x + h4.x, 0.0f);
        m.y = fmaxf(m.y + h4.y, 0.0f);
        m.z = fmaxf(m.z + h4.z, 0.0f);
        m.w = fmaxf(m.w + h4.w, 0.0f);
        float* p = g_AGG + d * DIM + 4 * sl;
        asm volatile("red.global.add.v4.f32 [%0], {%1, %2, %3, %4};"
                     :: "l"(p), "f"(m.x), "f"(m.y), "f"(m.z), "f"(m.w) : "memory");
    }
}

// ---------------- GEMM1: P1 = ((1+eps)*H + AGG) @ W1 + b1, epilogue: colsum/colsq
// Block: 64 rows x 128 cols, 256 threads, 8x4 tile/thread, packed f32x2 FMA.
__global__ void k_gemm1(const float* __restrict__ W1, const float* __restrict__ b1,
                        const float* __restrict__ epsp) {
    __shared__ float zs[64 * 68];    // transposed [k][r], pad 68
    __shared__ float ws[64 * 128];
    int t = threadIdx.x;
    int row0 = blockIdx.x * 64;
    float ev = 1.0f + __ldg(epsp);

    for (int i = t; i < 64 * 128; i += 256) ws[i] = W1[i];
    for (int i = t; i < 64 * 64; i += 256) {
        int r = i >> 6, k = i & 63;
        int gr = row0 + r;
        float v = 0.0f;
        if (gr < NNODES) v = ev * g_H[gr * 64 + k] + g_AGG[gr * 64 + k];
        zs[k * 68 + r] = v;
    }
    __syncthreads();

    int tx = t & 31, ty = t >> 5;
    int j4 = tx * 4, r8 = ty * 8;
    unsigned long long acc[8][2];
#pragma unroll
    for (int i = 0; i < 8; i++) { acc[i][0] = 0ULL; acc[i][1] = 0ULL; }

#pragma unroll 4
    for (int k = 0; k < 64; k++) {
        float4 wv = *(const float4*)(ws + k * 128 + j4);
        unsigned long long w01 = pk2(wv.x, wv.y);
        unsigned long long w23 = pk2(wv.z, wv.w);
        float4 za = *(const float4*)(zs + k * 68 + r8);
        float4 zb = *(const float4*)(zs + k * 68 + r8 + 4);
        unsigned long long z;
        z = pk2(za.x, za.x); fma2(acc[0][0], z, w01); fma2(acc[0][1], z, w23);
        z = pk2(za.y, za.y); fma2(acc[1][0], z, w01); fma2(acc[1][1], z, w23);
        z = pk2(za.z, za.z); fma2(acc[2][0], z, w01); fma2(acc[2][1], z, w23);
        z = pk2(za.w, za.w); fma2(acc[3][0], z, w01); fma2(acc[3][1], z, w23);
        z = pk2(zb.x, zb.x); fma2(acc[4][0], z, w01); fma2(acc[4][1], z, w23);
        z = pk2(zb.y, zb.y); fma2(acc[5][0], z, w01); fma2(acc[5][1], z, w23);
        z = pk2(zb.z, zb.z); fma2(acc[6][0], z, w01); fma2(acc[6][1], z, w23);
        z = pk2(zb.w, zb.w); fma2(acc[7][0], z, w01); fma2(acc[7][1], z, w23);
    }

    float4 bv = *(const float4*)(b1 + j4);
    float cs[4] = {0, 0, 0, 0}, cq[4] = {0, 0, 0, 0};
#pragma unroll
    for (int i = 0; i < 8; i++) {
        int gr = row0 + r8 + i;
        float o0, o1, o2, o3;
        upk2(acc[i][0], o0, o1);
        upk2(acc[i][1], o2, o3);
        o0 += bv.x; o1 += bv.y; o2 += bv.z; o3 += bv.w;
        if (gr < NNODES) {
            float4 o = make_float4(o0, o1, o2, o3);
            *(float4*)(g_P1 + gr * 128 + j4) = o;
            cs[0] += o0; cq[0] += o0 * o0;
            cs[1] += o1; cq[1] += o1 * o1;
            cs[2] += o2; cq[2] += o2 * o2;
            cs[3] += o3; cq[3] += o3 * o3;
        }
    }

    __syncthreads();  // done reading zs; reuse as reduction scratch
#pragma unroll
    for (int c = 0; c < 4; c++) {
        zs[ty * 128 + j4 + c] = cs[c];
        zs[1024 + ty * 128 + j4 + c] = cq[c];
    }
    __syncthreads();
    {
        int col = t & 127;
        int base = (t < 128) ? 0 : 1024;
        int off = (t < 128) ? 0 : 128;
        float v = 0.0f;
#pragma unroll
        for (int w = 0; w < 8; w++) v += zs[base + w * 128 + col];
        atomicAdd(g_stats + off + col, v);
    }
}

// -------- GEMM2: P2 = relu(BN1(P1)) @ W2 + b2, BN1 applied on A-load,
// epilogue: colsum/colsq for BN2. Block: 64 rows x 64 cols, 8x2 tile/thread.
__global__ void k_gemm2(const float* __restrict__ W2, const float* __restrict__ b2,
                        const float* __restrict__ g1v, const float* __restrict__ bb1v) {
    __shared__ float as[128 * 68];   // transposed [k][r], pad 68
    __shared__ float ws[128 * 64];
    __shared__ float sc[128], sh[128];
    int t = threadIdx.x;
    int row0 = blockIdx.x * 64;

    if (t < 128) {
        const float inv = 1.0f / (float)NNODES;
        float m = g_stats[t] * inv;
        float vq = g_stats[128 + t] * inv - m * m;
        float rs = rsqrtf(vq + BN_EPS);
        float s = rs * __ldg(g1v + t);
        sc[t] = s;
        sh[t] = __ldg(bb1v + t) - m * s;
    }
    for (int i = t; i < 128 * 64; i += 256) ws[i] = W2[i];
    __syncthreads();

    for (int i = t; i < 64 * 128; i += 256) {
        int r = i >> 7, k = i & 127;
        int gr = row0 + r;
        float v = 0.0f;
        if (gr < NNODES) v = fmaxf(g_P1[gr * 128 + k] * sc[k] + sh[k], 0.0f);
        as[k * 68 + r] = v;
    }
    __syncthreads();

    int tx = t & 31, ty = t >> 5;
    int j2 = tx * 2, r8 = ty * 8;
    unsigned long long acc[8];
#pragma unroll
    for (int i = 0; i < 8; i++) acc[i] = 0ULL;

#pragma unroll 4
    for (int k = 0; k < 128; k++) {
        float2 wv = *(const float2*)(ws + k * 64 + j2);
        unsigned long long wp = pk2(wv.x, wv.y);
        float4 za = *(const float4*)(as + k * 68 + r8);
        float4 zb = *(const float4*)(as + k * 68 + r8 + 4);
        unsigned long long z;
        z = pk2(za.x, za.x); fma2(acc[0], z, wp);
        z = pk2(za.y, za.y); fma2(acc[1], z, wp);
        z = pk2(za.z, za.z); fma2(acc[2], z, wp);
        z = pk2(za.w, za.w); fma2(acc[3], z, wp);
        z = pk2(zb.x, zb.x); fma2(acc[4], z, wp);
        z = pk2(zb.y, zb.y); fma2(acc[5], z, wp);
        z = pk2(zb.z, zb.z); fma2(acc[6], z, wp);
        z = pk2(zb.w, zb.w); fma2(acc[7], z, wp);
    }

    float2 bv = *(const float2*)(b2 + j2);
    float cs0 = 0, cs1 = 0, cq0 = 0, cq1 = 0;
#pragma unroll
    for (int i = 0; i < 8; i++) {
        int gr = row0 + r8 + i;
        float o0, o1;
        upk2(acc[i], o0, o1);
        o0 += bv.x; o1 += bv.y;
        if (gr < NNODES) {
            *(float2*)(g_P2 + gr * 64 + j2) = make_float2(o0, o1);
            cs0 += o0; cq0 += o0 * o0;
            cs1 += o1; cq1 += o1 * o1;
        }
    }

    __syncthreads();  // reuse as[] for reduction
    as[ty * 64 + j2] = cs0;       as[ty * 64 + j2 + 1] = cs1;
    as[512 + ty * 64 + j2] = cq0; as[512 + ty * 64 + j2 + 1] = cq1;
    __syncthreads();
    if (t < 128) {
        int col = t & 63;
        int base = (t < 64) ? 0 : 512;
        int off = (t < 64) ? 256 : 320;
        float v = 0.0f;
#pragma unroll
        for (int w = 0; w < 8; w++) v += as[base + w * 64 + col];
        atomicAdd(g_stats + off + col, v);
    }
}

// -------- BN2 (+optional ReLU): P2 -> H (intermediate, relu) or out (last),
// also zeroes AGG for next layer's edge accumulation.
__global__ void k_bn2(const float* __restrict__ g2v, const float* __restrict__ bb2v,
                      float* __restrict__ out, int relu) {
    int i = blockIdx.x * blockDim.x + threadIdx.x;
    if (i >= NNODES * 64) return;
    int j = i & 63;
    const float inv = 1.0f / (float)NNODES;
    float m = g_stats[256 + j] * inv;
    float vq = g_stats[320 + j] * inv - m * m;
    float rs = rsqrtf(vq + BN_EPS);
    float val = (g_P2[i] - m) * rs * __ldg(g2v + j) + __ldg(bb2v + j);
    if (relu) val = fmaxf(val, 0.0f);
    float* dst = out ? out : g_H;
    dst[i] = val;
    g_AGG[i] = 0.0f;
}

extern "C" void kernel_launch(void* const* d_in, const int* in_sizes, int n_in,
                              void* d_out, int out_size) {
    const int*   x   = (const int*)d_in[0];
    const int*   ei  = (const int*)d_in[1];     // [2,E]
    const float* ea  = (const float*)d_in[2];   // [E,7]
    const float* emb = (const float*)d_in[3];   // [1,64]
    const float* We  = (const float*)d_in[4];   // [L,7,64]
    const float* be  = (const float*)d_in[5];   // [L,64]
    const float* eps = (const float*)d_in[6];   // [L]
    const float* W1  = (const float*)d_in[7];   // [L,64,128]
    const float* b1  = (const float*)d_in[8];   // [L,128]
    const float* g1  = (const float*)d_in[9];   // [L,128]
    const float* bb1 = (const float*)d_in[10];  // [L,128]
    const float* W2  = (const float*)d_in[11];  // [L,128,64]
    const float* b2  = (const float*)d_in[12];  // [L,64]
    const float* g2  = (const float*)d_in[13];  // [L,64]
    const float* bb2 = (const float*)d_in[14];  // [L,64]
    float* out = (float*)d_out;

    const int elemBlocks64 = (NNODES * 64 + 255) / 256;   // 12500
    const int gemmBlocks   = (NNODES + 63) / 64;          // 782

    k_init<<<elemBlocks64, 256>>>(x, emb);

    for (int l = 0; l < LAYERS; l++) {
        k_edge<<<2048, 256>>>(ei, ea, We + l * 7 * 64, be + l * 64);
        k_gemm1<<<gemmBlocks, 256>>>(W1 + l * 64 * 128, b1 + l * 128, eps + l);
        k_gemm2<<<gemmBlocks, 256>>>(W2 + l * 128 * 64, b2 + l * 64,
                                     g1 + l * 128, bb1 + l * 128);
        if (l == LAYERS - 1) {
            k_bn2<<<elemBlocks64, 256>>>(g2 + l * 64, bb2 + l * 64, out, 0);
        } else {
            k_bn2<<<elemBlocks64, 256>>>(g2 + l * 64, bb2 + l * 64, nullptr, 1);
        }
    }
}

// round 5
// speedup vs baseline: 1.4236x; 1.0197x over previous
#include <cuda_runtime.h>

#define NNODES 50000
#define NEDGES 800000
#define DIM 64
#define LAYERS 5
#define BN_EPS 1e-5f

// Scratch (__device__ globals; allocation-free rule)
__device__ float g_H[NNODES * DIM];        // node features (layer input)
__device__ float g_AGG[NNODES * DIM];      // edge-aggregation accumulator
__device__ float g_P1[NNODES * 2 * DIM];   // hidden activations [N,128]
__device__ float g_P2[NNODES * DIM];       // mlp output pre-BN2 [N,64]
__device__ float g_stats[512];             // [0:128) sum1 [128:256) sq1 [256:320) sum2 [320:384) sq2

typedef unsigned long long u64;

// ---- packed f32x2 helpers ----
__device__ __forceinline__ u64 pkdup(float v) {         // (v, v)
    u64 r;
    asm("mov.b64 %0, {%1, %1};" : "=l"(r) : "f"(v));
    return r;
}
__device__ __forceinline__ void upk2(u64 v, float& lo, float& hi) {
    asm("mov.b64 {%0, %1}, %2;" : "=f"(lo), "=f"(hi) : "l"(v));
}
__device__ __forceinline__ void fma2(u64& d, u64 a, u64 b) {
    asm("fma.rn.f32x2 %0, %1, %2, %3;" : "=l"(d) : "l"(a), "l"(b), "l"(d));
}

// ---------------------------------------------------------------- init
__global__ void k_init(const int* __restrict__ x, const float* __restrict__ emb) {
    int i = blockIdx.x * blockDim.x + threadIdx.x;
    if (i < 512) g_stats[i] = 0.0f;
    if (i < NNODES * DIM) {
        int n = i >> 6, d = i & 63;
        g_H[i] = emb[x[n] * DIM + d];
        g_AGG[i] = 0.0f;
    }
}

// -------- edge stage: AGG[dst] += relu(h[src] + ea@We + be). Half-warp per edge,
// lane owns 4 features, one red.global.add.v4.f32 per lane (16 REDs/edge).
// Block 0 also zeroes ALL 512 stats entries for this layer.
__global__ void k_edge(const int* __restrict__ ei, const float* __restrict__ ea,
                       const float* __restrict__ We, const float* __restrict__ be) {
    if (blockIdx.x == 0) {
        g_stats[threadIdx.x] = 0.0f;
        g_stats[256 + threadIdx.x] = 0.0f;
    }

    int t = blockIdx.x * blockDim.x + threadIdx.x;
    int lane = t & 31;
    int sub = lane >> 4;          // 0/1: which edge of this warp's pair
    int sl = lane & 15;           // feature group: 4 floats
    int warp = t >> 5;
    int nslots = (gridDim.x * blockDim.x) >> 4;   // 2 edges per warp

    float4 w[7];
#pragma unroll
    for (int k = 0; k < 7; k++) w[k] = *(const float4*)(We + k * DIM + 4 * sl);
    float4 b4 = *(const float4*)(be + 4 * sl);

#pragma unroll 2
    for (int e = warp * 2 + sub; e < NEDGES; e += nslots) {
        int s = __ldg(ei + e);
        int d = __ldg(ei + NEDGES + e);
        const float* ep = ea + e * 7;
        float4 m = b4;
#pragma unroll
        for (int k = 0; k < 7; k++) {
            float a = __ldg(ep + k);
            m.x = fmaf(a, w[k].x, m.x);
            m.y = fmaf(a, w[k].y, m.y);
            m.z = fmaf(a, w[k].z, m.z);
            m.w = fmaf(a, w[k].w, m.w);
        }
        float4 h4 = *(const float4*)(g_H + s * DIM + 4 * sl);
        m.x = fmaxf(m.x + h4.x, 0.0f);
        m.y = fmaxf(m.y + h4.y, 0.0f);
        m.z = fmaxf(m.z + h4.z, 0.0f);
        m.w = fmaxf(m.w + h4.w, 0.0f);
        float* p = g_AGG + d * DIM + 4 * sl;
        asm volatile("red.global.add.v4.f32 [%0], {%1, %2, %3, %4};"
                     :: "l"(p), "f"(m.x), "f"(m.y), "f"(m.z), "f"(m.w) : "memory");
    }
}

// ---------------- GEMM1: P1 = ((1+eps)*H + AGG) @ W1 + b1, epilogue: colsum/colsq
// Block: 64 rows x 128 cols, 256 threads, 8x4 tile/thread.
// Row-pair f32x2 packing: z-pairs read directly as u64 from transposed smem.
__global__ void k_gemm1(const float* __restrict__ W1, const float* __restrict__ b1,
                        const float* __restrict__ epsp) {
    __shared__ float zs[64 * 68];    // transposed [k][r], pad 68 (68%4==0 keeps 16B align)
    __shared__ float ws[64 * 128];
    int t = threadIdx.x;
    int row0 = blockIdx.x * 64;
    float ev = 1.0f + __ldg(epsp);

    for (int i = t; i < 64 * 128; i += 256) ws[i] = W1[i];
    for (int i = t; i < 64 * 64; i += 256) {
        int r = i >> 6, k = i & 63;
        int gr = row0 + r;
        float v = 0.0f;
        if (gr < NNODES) v = ev * g_H[gr * 64 + k] + g_AGG[gr * 64 + k];
        zs[k * 68 + r] = v;
    }
    __syncthreads();

    int tx = t & 31, ty = t >> 5;
    int j4 = tx * 4, r8 = ty * 8;
    u64 acc[4][4];                  // [row-pair p][col c]: rows (r8+2p, r8+2p+1)
#pragma unroll
    for (int p = 0; p < 4; p++)
#pragma unroll
        for (int c = 0; c < 4; c++) acc[p][c] = 0ULL;

#pragma unroll 4
    for (int k = 0; k < 64; k++) {
        float4 wv = *(const float4*)(ws + k * 128 + j4);
        u64 wd[4] = {pkdup(wv.x), pkdup(wv.y), pkdup(wv.z), pkdup(wv.w)};
        ulonglong2 za = *(const ulonglong2*)(zs + k * 68 + r8);     // pairs 0,1
        ulonglong2 zb = *(const ulonglong2*)(zs + k * 68 + r8 + 4); // pairs 2,3
        u64 zp[4] = {za.x, za.y, zb.x, zb.y};
#pragma unroll
        for (int p = 0; p < 4; p++) {
            fma2(acc[p][0], zp[p], wd[0]);
            fma2(acc[p][1], zp[p], wd[1]);
            fma2(acc[p][2], zp[p], wd[2]);
            fma2(acc[p][3], zp[p], wd[3]);
        }
    }

    float4 bv = *(const float4*)(b1 + j4);
    float cs[4] = {0, 0, 0, 0}, cq[4] = {0, 0, 0, 0};
#pragma unroll
    for (int p = 0; p < 4; p++) {
        float o[2][4];
#pragma unroll
        for (int c = 0; c < 4; c++) upk2(acc[p][c], o[0][c], o[1][c]);
#pragma unroll
        for (int h = 0; h < 2; h++) {
            int gr = row0 + r8 + 2 * p + h;
            float o0 = o[h][0] + bv.x, o1 = o[h][1] + bv.y;
            float o2 = o[h][2] + bv.z, o3 = o[h][3] + bv.w;
            if (gr < NNODES) {
                *(float4*)(g_P1 + gr * 128 + j4) = make_float4(o0, o1, o2, o3);
                cs[0] += o0; cq[0] += o0 * o0;
                cs[1] += o1; cq[1] += o1 * o1;
                cs[2] += o2; cq[2] += o2 * o2;
                cs[3] += o3; cq[3] += o3 * o3;
            }
        }
    }

    __syncthreads();  // reuse zs as reduction scratch
#pragma unroll
    for (int c = 0; c < 4; c++) {
        zs[ty * 128 + j4 + c] = cs[c];
        zs[1024 + ty * 128 + j4 + c] = cq[c];
    }
    __syncthreads();
    {
        int col = t & 127;
        int base = (t < 128) ? 0 : 1024;
        int off = (t < 128) ? 0 : 128;
        float v = 0.0f;
#pragma unroll
        for (int w = 0; w < 8; w++) v += zs[base + w * 128 + col];
        atomicAdd(g_stats + off + col, v);
    }
}

// -------- GEMM2: P2 = relu(BN1(P1)) @ W2 + b2, BN1 applied on A-load,
// epilogue: colsum/colsq for BN2. Block: 64 rows x 64 cols, 8x2 tile/thread.
__global__ void k_gemm2(const float* __restrict__ W2, const float* __restrict__ b2,
                        const float* __restrict__ g1v, const float* __restrict__ bb1v) {
    __shared__ float as[128 * 68];   // transposed [k][r], pad 68
    __shared__ float ws[128 * 64];
    __shared__ float sc[128], sh[128];
    int t = threadIdx.x;
    int row0 = blockIdx.x * 64;

    if (t < 128) {
        const float inv = 1.0f / (float)NNODES;
        float m = g_stats[t] * inv;
        float vq = g_stats[128 + t] * inv - m * m;
        float rs = rsqrtf(vq + BN_EPS);
        float s = rs * __ldg(g1v + t);
        sc[t] = s;
        sh[t] = __ldg(bb1v + t) - m * s;
    }
    for (int i = t; i < 128 * 64; i += 256) ws[i] = W2[i];
    __syncthreads();

    for (int i = t; i < 64 * 128; i += 256) {
        int r = i >> 7, k = i & 127;
        int gr = row0 + r;
        float v = 0.0f;
        if (gr < NNODES) v = fmaxf(g_P1[gr * 128 + k] * sc[k] + sh[k], 0.0f);
        as[k * 68 + r] = v;
    }
    __syncthreads();

    int tx = t & 31, ty = t >> 5;
    int j2 = tx * 2, r8 = ty * 8;
    u64 acc[4][2];                  // [row-pair][col]
#pragma unroll
    for (int p = 0; p < 4; p++) { acc[p][0] = 0ULL; acc[p][1] = 0ULL; }

#pragma unroll 4
    for (int k = 0; k < 128; k++) {
        float2 wv = *(const float2*)(ws + k * 64 + j2);
        u64 w0 = pkdup(wv.x), w1 = pkdup(wv.y);
        ulonglong2 za = *(const ulonglong2*)(as + k * 68 + r8);
        ulonglong2 zb = *(const ulonglong2*)(as + k * 68 + r8 + 4);
        u64 zp[4] = {za.x, za.y, zb.x, zb.y};
#pragma unroll
        for (int p = 0; p < 4; p++) {
            fma2(acc[p][0], zp[p], w0);
            fma2(acc[p][1], zp[p], w1);
        }
    }

    float2 bv = *(const float2*)(b2 + j2);
    float cs0 = 0, cs1 = 0, cq0 = 0, cq1 = 0;
#pragma unroll
    for (int p = 0; p < 4; p++) {
        float a0, a1, b0h, b1h;
        upk2(acc[p][0], a0, b0h);   // col0: rows 2p, 2p+1
        upk2(acc[p][1], a1, b1h);   // col1
#pragma unroll
        for (int h = 0; h < 2; h++) {
            int gr = row0 + r8 + 2 * p + h;
            float o0 = (h ? b0h : a0) + bv.x;
            float o1 = (h ? b1h : a1) + bv.y;
            if (gr < NNODES) {
                *(float2*)(g_P2 + gr * 64 + j2) = make_float2(o0, o1);
                cs0 += o0; cq0 += o0 * o0;
                cs1 += o1; cq1 += o1 * o1;
            }
        }
    }

    __syncthreads();  // reuse as[] for reduction
    as[ty * 64 + j2] = cs0;       as[ty * 64 + j2 + 1] = cs1;
    as[512 + ty * 64 + j2] = cq0; as[512 + ty * 64 + j2 + 1] = cq1;
    __syncthreads();
    if (t < 128) {
        int col = t & 63;
        int base = (t < 64) ? 0 : 512;
        int off = (t < 64) ? 256 : 320;
        float v = 0.0f;
#pragma unroll
        for (int w = 0; w < 8; w++) v += as[base + w * 64 + col];
        atomicAdd(g_stats + off + col, v);
    }
}

// -------- BN2 (+optional ReLU): P2 -> H (intermediate, relu) or out (last),
// also zeroes AGG for next layer's edge accumulation.
__global__ void k_bn2(const float* __restrict__ g2v, const float* __restrict__ bb2v,
                      float* __restrict__ out, int relu) {
    int i = blockIdx.x * blockDim.x + threadIdx.x;
    if (i >= NNODES * 64) return;
    int j = i & 63;
    const float inv = 1.0f / (float)NNODES;
    float m = g_stats[256 + j] * inv;
    float vq = g_stats[320 + j] * inv - m * m;
    float rs = rsqrtf(vq + BN_EPS);
    float val = (g_P2[i] - m) * rs * __ldg(g2v + j) + __ldg(bb2v + j);
    if (relu) val = fmaxf(val, 0.0f);
    float* dst = out ? out : g_H;
    dst[i] = val;
    g_AGG[i] = 0.0f;
}

extern "C" void kernel_launch(void* const* d_in, const int* in_sizes, int n_in,
                              void* d_out, int out_size) {
    const int*   x   = (const int*)d_in[0];
    const int*   ei  = (const int*)d_in[1];     // [2,E]
    const float* ea  = (const float*)d_in[2];   // [E,7]
    const float* emb = (const float*)d_in[3];   // [1,64]
    const float* We  = (const float*)d_in[4];   // [L,7,64]
    const float* be  = (const float*)d_in[5];   // [L,64]
    const float* eps = (const float*)d_in[6];   // [L]
    const float* W1  = (const float*)d_in[7];   // [L,64,128]
    const float* b1  = (const float*)d_in[8];   // [L,128]
    const float* g1  = (const float*)d_in[9];   // [L,128]
    const float* bb1 = (const float*)d_in[10];  // [L,128]
    const float* W2  = (const float*)d_in[11];  // [L,128,64]
    const float* b2  = (const float*)d_in[12];  // [L,64]
    const float* g2  = (const float*)d_in[13];  // [L,64]
    const float* bb2 = (const float*)d_in[14];  // [L,64]
    float* out = (float*)d_out;

    const int elemBlocks64 = (NNODES * 64 + 255) / 256;   // 12500
    const int gemmBlocks   = (NNODES + 63) / 64;          // 782

    k_init<<<elemBlocks64, 256>>>(x, emb);

    for (int l = 0; l < LAYERS; l++) {
        k_edge<<<2048, 256>>>(ei, ea, We + l * 7 * 64, be + l * 64);
        k_gemm1<<<gemmBlocks, 256>>>(W1 + l * 64 * 128, b1 + l * 128, eps + l);
        k_gemm2<<<gemmBlocks, 256>>>(W2 + l * 128 * 64, b2 + l * 64,
                                     g1 + l * 128, bb1 + l * 128);
        if (l == LAYERS - 1) {
            k_bn2<<<elemBlocks64, 256>>>(g2 + l * 64, bb2 + l * 64, out, 0);
        } else {
            k_bn2<<<elemBlocks64, 256>>>(g2 + l * 64, bb2 + l * 64, nullptr, 1);
        }
    }
}

// round 6
// speedup vs baseline: 1.4981x; 1.0524x over previous
#include <cuda_runtime.h>

#define NNODES 50000
#define NEDGES 800000
#define DIM 64
#define LAYERS 5
#define BN_EPS 1e-5f
#define SCAN_BLOCKS 196   // ceil(50000/256)

// Scratch (__device__ globals; allocation-free rule)
__device__ float g_H[NNODES * DIM];        // node features (layer input)
__device__ float g_Z[NNODES * DIM];        // (1+eps)*h + agg  (GEMM1 input)
__device__ float g_P1[NNODES * 2 * DIM];   // hidden activations [N,128]
__device__ float g_P2[NNODES * DIM];       // mlp output pre-BN2 [N,64]
__device__ float g_stats[512];             // [0:128) sum1 [128:256) sq1 [256:320) sum2 [320:384) sq2
__device__ int   g_deg[NNODES];            // per-dst degree
__device__ int   g_off[NNODES];            // CSR row offsets (exclusive)
__device__ int   g_cur[NNODES];            // scatter cursors
__device__ int   g_csr[NEDGES];            // edge ids grouped by dst
__device__ int   g_bsum[256];              // scan block sums

typedef unsigned long long u64;

// ---- packed f32x2 helpers ----
__device__ __forceinline__ u64 pkdup(float v) {
    u64 r;
    asm("mov.b64 %0, {%1, %1};" : "=l"(r) : "f"(v));
    return r;
}
__device__ __forceinline__ void upk2(u64 v, float& lo, float& hi) {
    asm("mov.b64 {%0, %1}, %2;" : "=f"(lo), "=f"(hi) : "l"(v));
}
__device__ __forceinline__ void fma2(u64& d, u64 a, u64 b) {
    asm("fma.rn.f32x2 %0, %1, %2, %3;" : "=l"(d) : "l"(a), "l"(b), "l"(d));
}

// ---------------------------------------------------------------- init
__global__ void k_init(const int* __restrict__ x, const float* __restrict__ emb) {
    int i = blockIdx.x * blockDim.x + threadIdx.x;
    if (i < 512) g_stats[i] = 0.0f;
    if (i < NNODES) g_deg[i] = 0;
    if (i < NNODES * DIM) {
        int n = i >> 6, d = i & 63;
        g_H[i] = emb[x[n] * DIM + d];
    }
}

// ---------------------------------------------------- CSR build (per call)
__global__ void k_hist(const int* __restrict__ ei) {
    int e = blockIdx.x * blockDim.x + threadIdx.x;
    if (e < NEDGES) atomicAdd(&g_deg[__ldg(ei + NEDGES + e)], 1);
}

// Block-level exclusive scan of g_deg -> g_off (local), block totals -> g_bsum
__global__ void k_scanA() {
    __shared__ int ws[8];
    int i = blockIdx.x * 256 + threadIdx.x;
    int lane = threadIdx.x & 31, w = threadIdx.x >> 5;
    int v = (i < NNODES) ? g_deg[i] : 0;
    int x = v;
#pragma unroll
    for (int o = 1; o < 32; o <<= 1) {
        int y = __shfl_up_sync(0xFFFFFFFFu, x, o);
        if (lane >= o) x += y;
    }
    if (lane == 31) ws[w] = x;
    __syncthreads();
    if (w == 0) {
        int y = (lane < 8) ? ws[lane] : 0;
#pragma unroll
        for (int o = 1; o < 8; o <<= 1) {
            int z = __shfl_up_sync(0xFFFFFFFFu, y, o);
            if (lane >= o) y += z;
        }
        if (lane < 8) ws[lane] = y;
    }
    __syncthreads();
    int base = (w > 0) ? ws[w - 1] : 0;
    int incl = x + base;
    if (i < NNODES) g_off[i] = incl - v;            // exclusive within block
    if (threadIdx.x == 255) g_bsum[blockIdx.x] = incl;
}

// Exclusive scan of the SCAN_BLOCKS block sums (single block)
__global__ void k_scanB() {
    __shared__ int ws[8];
    int t = threadIdx.x;
    int lane = t & 31, w = t >> 5;
    int v = (t < SCAN_BLOCKS) ? g_bsum[t] : 0;
    int x = v;
#pragma unroll
    for (int o = 1; o < 32; o <<= 1) {
        int y = __shfl_up_sync(0xFFFFFFFFu, x, o);
        if (lane >= o) x += y;
    }
    if (lane == 31) ws[w] = x;
    __syncthreads();
    if (w == 0) {
        int y = (lane < 8) ? ws[lane] : 0;
#pragma unroll
        for (int o = 1; o < 8; o <<= 1) {
            int z = __shfl_up_sync(0xFFFFFFFFu, y, o);
            if (lane >= o) y += z;
        }
        if (lane < 8) ws[lane] = y;
    }
    __syncthreads();
    int base = (w > 0) ? ws[w - 1] : 0;
    if (t < SCAN_BLOCKS) g_bsum[t] = x + base - v;  // exclusive
}

__global__ void k_scanC() {
    int i = blockIdx.x * 256 + threadIdx.x;
    if (i < NNODES) {
        g_off[i] += g_bsum[blockIdx.x];
        g_cur[i] = 0;
    }
}

__global__ void k_scatter(const int* __restrict__ ei) {
    int e = blockIdx.x * blockDim.x + threadIdx.x;
    if (e < NEDGES) {
        int d = __ldg(ei + NEDGES + e);
        int p = atomicAdd(&g_cur[d], 1);
        g_csr[g_off[d] + p] = e;
    }
}

// -------- aggregation: one warp per node, no atomics.
// Z[n] = (1+eps)*H[n] + sum_{e: dst=n} relu(H[src(e)] + ea[e]@We + be)
// Lane owns 2 features. Block 0 zeroes stats for this layer.
__global__ void k_aggr(const int* __restrict__ ei, const float* __restrict__ ea,
                       const float* __restrict__ We, const float* __restrict__ be,
                       const float* __restrict__ epsp) {
    if (blockIdx.x == 0) {
        g_stats[threadIdx.x] = 0.0f;
        g_stats[256 + threadIdx.x] = 0.0f;
    }
    int node = (blockIdx.x * blockDim.x + threadIdx.x) >> 5;
    if (node >= NNODES) return;
    int lane = threadIdx.x & 31;

    float2 w[7];
#pragma unroll
    for (int k = 0; k < 7; k++) w[k] = *(const float2*)(We + k * DIM + 2 * lane);
    float2 bv = *(const float2*)(be + 2 * lane);

    int beg = g_off[node];
    int end = (node == NNODES - 1) ? NEDGES : g_off[node + 1];

    float a0 = 0.0f, a1 = 0.0f;
#pragma unroll 2
    for (int p = beg; p < end; p++) {
        int e = __ldg(g_csr + p);
        int s = __ldg(ei + e);
        const float* ep = ea + e * 7;
        float m0 = bv.x, m1 = bv.y;
#pragma unroll
        for (int k = 0; k < 7; k++) {
            float a = __ldg(ep + k);
            m0 = fmaf(a, w[k].x, m0);
            m1 = fmaf(a, w[k].y, m1);
        }
        float2 h2 = *(const float2*)(g_H + s * DIM + 2 * lane);
        a0 += fmaxf(m0 + h2.x, 0.0f);
        a1 += fmaxf(m1 + h2.y, 0.0f);
    }

    float ev = 1.0f + __ldg(epsp);
    float2 hh = *(const float2*)(g_H + node * DIM + 2 * lane);
    *(float2*)(g_Z + node * DIM + 2 * lane) =
        make_float2(fmaf(ev, hh.x, a0), fmaf(ev, hh.y, a1));
}

// ---------------- GEMM1: P1 = Z @ W1 + b1, epilogue: colsum/colsq
__global__ void k_gemm1(const float* __restrict__ W1, const float* __restrict__ b1) {
    __shared__ float zs[64 * 68];    // transposed [k][r]
    __shared__ float ws[64 * 128];
    int t = threadIdx.x;
    int row0 = blockIdx.x * 64;

    for (int i = t; i < 64 * 128; i += 256) ws[i] = W1[i];
    for (int i = t; i < 64 * 64; i += 256) {
        int r = i >> 6, k = i & 63;
        int gr = row0 + r;
        zs[k * 68 + r] = (gr < NNODES) ? g_Z[gr * 64 + k] : 0.0f;
    }
    __syncthreads();

    int tx = t & 31, ty = t >> 5;
    int j4 = tx * 4, r8 = ty * 8;
    u64 acc[4][4];
#pragma unroll
    for (int p = 0; p < 4; p++)
#pragma unroll
        for (int c = 0; c < 4; c++) acc[p][c] = 0ULL;

#pragma unroll 4
    for (int k = 0; k < 64; k++) {
        float4 wv = *(const float4*)(ws + k * 128 + j4);
        u64 wd[4] = {pkdup(wv.x), pkdup(wv.y), pkdup(wv.z), pkdup(wv.w)};
        ulonglong2 za = *(const ulonglong2*)(zs + k * 68 + r8);
        ulonglong2 zb = *(const ulonglong2*)(zs + k * 68 + r8 + 4);
        u64 zp[4] = {za.x, za.y, zb.x, zb.y};
#pragma unroll
        for (int p = 0; p < 4; p++) {
            fma2(acc[p][0], zp[p], wd[0]);
            fma2(acc[p][1], zp[p], wd[1]);
            fma2(acc[p][2], zp[p], wd[2]);
            fma2(acc[p][3], zp[p], wd[3]);
        }
    }

    float4 bv = *(const float4*)(b1 + j4);
    float cs[4] = {0, 0, 0, 0}, cq[4] = {0, 0, 0, 0};
#pragma unroll
    for (int p = 0; p < 4; p++) {
        float o[2][4];
#pragma unroll
        for (int c = 0; c < 4; c++) upk2(acc[p][c], o[0][c], o[1][c]);
#pragma unroll
        for (int h = 0; h < 2; h++) {
            int gr = row0 + r8 + 2 * p + h;
            float o0 = o[h][0] + bv.x, o1 = o[h][1] + bv.y;
            float o2 = o[h][2] + bv.z, o3 = o[h][3] + bv.w;
            if (gr < NNODES) {
                *(float4*)(g_P1 + gr * 128 + j4) = make_float4(o0, o1, o2, o3);
                cs[0] += o0; cq[0] += o0 * o0;
                cs[1] += o1; cq[1] += o1 * o1;
                cs[2] += o2; cq[2] += o2 * o2;
                cs[3] += o3; cq[3] += o3 * o3;
            }
        }
    }

    __syncthreads();
#pragma unroll
    for (int c = 0; c < 4; c++) {
        zs[ty * 128 + j4 + c] = cs[c];
        zs[1024 + ty * 128 + j4 + c] = cq[c];
    }
    __syncthreads();
    {
        int col = t & 127;
        int base = (t < 128) ? 0 : 1024;
        int off = (t < 128) ? 0 : 128;
        float v = 0.0f;
#pragma unroll
        for (int w = 0; w < 8; w++) v += zs[base + w * 128 + col];
        atomicAdd(g_stats + off + col, v);
    }
}

// -------- GEMM2: P2 = relu(BN1(P1)) @ W2 + b2, epilogue colsum/colsq for BN2
__global__ void k_gemm2(const float* __restrict__ W2, const float* __restrict__ b2,
                        const float* __restrict__ g1v, const float* __restrict__ bb1v) {
    __shared__ float as[128 * 68];
    __shared__ float ws[128 * 64];
    __shared__ float sc[128], sh[128];
    int t = threadIdx.x;
    int row0 = blockIdx.x * 64;

    if (t < 128) {
        const float inv = 1.0f / (float)NNODES;
        float m = g_stats[t] * inv;
        float vq = g_stats[128 + t] * inv - m * m;
        float rs = rsqrtf(vq + BN_EPS);
        float s = rs * __ldg(g1v + t);
        sc[t] = s;
        sh[t] = __ldg(bb1v + t) - m * s;
    }
    for (int i = t; i < 128 * 64; i += 256) ws[i] = W2[i];
    __syncthreads();

    for (int i = t; i < 64 * 128; i += 256) {
        int r = i >> 7, k = i & 127;
        int gr = row0 + r;
        float v = 0.0f;
        if (gr < NNODES) v = fmaxf(g_P1[gr * 128 + k] * sc[k] + sh[k], 0.0f);
        as[k * 68 + r] = v;
    }
    __syncthreads();

    int tx = t & 31, ty = t >> 5;
    int j2 = tx * 2, r8 = ty * 8;
    u64 acc[4][2];
#pragma unroll
    for (int p = 0; p < 4; p++) { acc[p][0] = 0ULL; acc[p][1] = 0ULL; }

#pragma unroll 4
    for (int k = 0; k < 128; k++) {
        float2 wv = *(const float2*)(ws + k * 64 + j2);
        u64 w0 = pkdup(wv.x), w1 = pkdup(wv.y);
        ulonglong2 za = *(const ulonglong2*)(as + k * 68 + r8);
        ulonglong2 zb = *(const ulonglong2*)(as + k * 68 + r8 + 4);
        u64 zp[4] = {za.x, za.y, zb.x, zb.y};
#pragma unroll
        for (int p = 0; p < 4; p++) {
            fma2(acc[p][0], zp[p], w0);
            fma2(acc[p][1], zp[p], w1);
        }
    }

    float2 bv = *(const float2*)(b2 + j2);
    float cs0 = 0, cs1 = 0, cq0 = 0, cq1 = 0;
#pragma unroll
    for (int p = 0; p < 4; p++) {
        float a0, a1, b0h, b1h;
        upk2(acc[p][0], a0, b0h);
        upk2(acc[p][1], a1, b1h);
#pragma unroll
        for (int h = 0; h < 2; h++) {
            int gr = row0 + r8 + 2 * p + h;
            float o0 = (h ? b0h : a0) + bv.x;
            float o1 = (h ? b1h : a1) + bv.y;
            if (gr < NNODES) {
                *(float2*)(g_P2 + gr * 64 + j2) = make_float2(o0, o1);
                cs0 += o0; cq0 += o0 * o0;
                cs1 += o1; cq1 += o1 * o1;
            }
        }
    }

    __syncthreads();
    as[ty * 64 + j2] = cs0;       as[ty * 64 + j2 + 1] = cs1;
    as[512 + ty * 64 + j2] = cq0; as[512 + ty * 64 + j2 + 1] = cq1;
    __syncthreads();
    if (t < 128) {
        int col = t & 63;
        int base = (t < 64) ? 0 : 512;
        int off = (t < 64) ? 256 : 320;
        float v = 0.0f;
#pragma unroll
        for (int w = 0; w < 8; w++) v += as[base + w * 64 + col];
        atomicAdd(g_stats + off + col, v);
    }
}

// -------- BN2 (+optional ReLU): P2 -> H (intermediate, relu) or out (last)
__global__ void k_bn2(const float* __restrict__ g2v, const float* __restrict__ bb2v,
                      float* __restrict__ out, int relu) {
    int i = blockIdx.x * blockDim.x + threadIdx.x;
    if (i >= NNODES * 64) return;
    int j = i & 63;
    const float inv = 1.0f / (float)NNODES;
    float m = g_stats[256 + j] * inv;
    float vq = g_stats[320 + j] * inv - m * m;
    float rs = rsqrtf(vq + BN_EPS);
    float val = (g_P2[i] - m) * rs * __ldg(g2v + j) + __ldg(bb2v + j);
    if (relu) val = fmaxf(val, 0.0f);
    float* dst = out ? out : g_H;
    dst[i] = val;
}

extern "C" void kernel_launch(void* const* d_in, const int* in_sizes, int n_in,
                              void* d_out, int out_size) {
    const int*   x   = (const int*)d_in[0];
    const int*   ei  = (const int*)d_in[1];     // [2,E]
    const float* ea  = (const float*)d_in[2];   // [E,7]
    const float* emb = (const float*)d_in[3];   // [1,64]
    const float* We  = (const float*)d_in[4];   // [L,7,64]
    const float* be  = (const float*)d_in[5];   // [L,64]
    const float* eps = (const float*)d_in[6];   // [L]
    const float* W1  = (const float*)d_in[7];   // [L,64,128]
    const float* b1  = (const float*)d_in[8];   // [L,128]
    const float* g1  = (const float*)d_in[9];   // [L,128]
    const float* bb1 = (const float*)d_in[10];  // [L,128]
    const float* W2  = (const float*)d_in[11];  // [L,128,64]
    const float* b2  = (const float*)d_in[12];  // [L,64]
    const float* g2  = (const float*)d_in[13];  // [L,64]
    const float* bb2 = (const float*)d_in[14];  // [L,64]
    float* out = (float*)d_out;

    const int elemBlocks64 = (NNODES * 64 + 255) / 256;   // 12500
    const int gemmBlocks   = (NNODES + 63) / 64;          // 782
    const int edgeBlocks   = (NEDGES + 255) / 256;        // 3125
    const int aggrBlocks   = (NNODES * 32 + 255) / 256;   // 6250

    // CSR build (dst-grouped edge lists; edge_index constant across layers)
    k_init<<<elemBlocks64, 256>>>(x, emb);
    k_hist<<<edgeBlocks, 256>>>(ei);
    k_scanA<<<SCAN_BLOCKS, 256>>>();
    k_scanB<<<1, 256>>>();
    k_scanC<<<SCAN_BLOCKS, 256>>>();
    k_scatter<<<edgeBlocks, 256>>>(ei);

    for (int l = 0; l < LAYERS; l++) {
        k_aggr<<<aggrBlocks, 256>>>(ei, ea, We + l * 7 * 64, be + l * 64, eps + l);
        k_gemm1<<<gemmBlocks, 256>>>(W1 + l * 64 * 128, b1 + l * 128);
        k_gemm2<<<gemmBlocks, 256>>>(W2 + l * 128 * 64, b2 + l * 64,
                                     g1 + l * 128, bb1 + l * 128);
        if (l == LAYERS - 1) {
            k_bn2<<<elemBlocks64, 256>>>(g2 + l * 64, bb2 + l * 64, out, 0);
        } else {
            k_bn2<<<elemBlocks64, 256>>>(g2 + l * 64, bb2 + l * 64, nullptr, 1);
        }
    }
}